// round 1
// baseline (speedup 1.0000x reference)
#include <cuda_runtime.h>
#include <math.h>

#define Bc      8
#define Nc      1024
#define NTYPESc 2
#define MNc     128
#define Mc      256          // NTYPES*MN
#define BETAc   8
#define M1c     16
#define M2c     4
#define NFEATc  64           // M1*M2
#define Hc      128
#define NGHOSTc 64
#define NTOT    (Nc + NGHOSTc)   // 1088
#define RMAXc   6.0f
#define RMINc   0.5f
#define SPANc   5.5f
#define PI_F    3.14159265358979323846f

#define O_ETOT  0
#define O_EI    (O_ETOT + Bc)                 // 8
#define O_FORCE (O_EI + Bc*Nc)                // 8200
#define O_VIR   (O_FORCE + Bc*NTOT*3)         // 34312
#define OUT_TOTAL (O_VIR + Bc*9)              // 34384

// ---------------- device scratch (no allocation allowed) ----------------
__device__ float  g_S    [Bc*Nc*NFEATc];   // S (B,N,16,4), already /M
__device__ float  g_feat [Bc*Nc*NFEATc];   // raw features
__device__ float  g_dfeat[Bc*Nc*NFEATc];   // dE/dfeat_raw (incl. 1/std)
__device__ double g_sum  [NTYPESc];
__device__ double g_sumsq[NTYPESc];
__device__ float  g_mu   [NTYPESc];
__device__ float  g_istd [NTYPESc];        // 1/std
__device__ float  g_W0T  [NTYPESc*Hc*NFEATc];  // [t][j][p]
__device__ float  g_W1T  [NTYPESc*Hc*Hc];      // [t][j][i]
__device__ float  g_W2T  [NTYPESc*Hc*Hc];

__device__ __forceinline__ float wsum(float v) {
    v += __shfl_xor_sync(0xffffffffu, v, 16);
    v += __shfl_xor_sync(0xffffffffu, v, 8);
    v += __shfl_xor_sync(0xffffffffu, v, 4);
    v += __shfl_xor_sync(0xffffffffu, v, 2);
    v += __shfl_xor_sync(0xffffffffu, v, 1);
    return v;
}

// ---------------- kernel 0: zero outputs + accumulators -----------------
__global__ void zero_kernel(float* out) {
    int i = blockIdx.x * blockDim.x + threadIdx.x;
    if (i < OUT_TOTAL) out[i] = 0.0f;
    if (i < NTYPESc) { g_sum[i] = 0.0; g_sumsq[i] = 0.0; }
}

// ---------------- kernel 1: transpose weights for coalesced backward ----
__global__ void transpose_kernel(const float* __restrict__ W0,
                                 const float* __restrict__ W1,
                                 const float* __restrict__ W2) {
    int i = blockIdx.x * blockDim.x + threadIdx.x;
    if (i < NTYPESc*Hc*NFEATc) {
        int t = i / (Hc*NFEATc); int r = i % (Hc*NFEATc);
        int j = r / NFEATc;      int p = r % NFEATc;
        g_W0T[i] = W0[(t*NFEATc + p)*Hc + j];
    }
    if (i < NTYPESc*Hc*Hc) {
        int t = i / (Hc*Hc); int r = i % (Hc*Hc);
        int j = r / Hc;      int k = r % Hc;
        g_W1T[i] = W1[(t*Hc + k)*Hc + j];
        g_W2T[i] = W2[(t*Hc + k)*Hc + j];
    }
}

// ---------------- kernel 2: features + per-type stats --------------------
// one block per (b,n); 256 threads, one per neighbor m
__global__ void feat_kernel(const float* __restrict__ rvec,
                            const int*   __restrict__ tmap,
                            const float* __restrict__ cparam) {
    int bn = blockIdx.x;
    int n  = bn & (Nc - 1);
    int m  = threadIdx.x;
    int ti = tmap[n];

    __shared__ float c_sh[NTYPESc*M1c*BETAc];   // 256
    __shared__ float S_sh[NFEATc];
    __shared__ float Sn[NFEATc];
    __shared__ float ps[8], ps2[8];

    c_sh[m] = cparam[ti * (NTYPESc*M1c*BETAc) + m];
    if (m < NFEATc) S_sh[m] = 0.0f;
    __syncthreads();

    const float* rv = rvec + ((long)bn * Mc + m) * 3;
    float x = rv[0], y = rv[1], z = rv[2];
    float r = sqrtf(x*x + y*y + z*z);
    bool  valid = r > 1e-6f;
    float rs  = valid ? r : 1.0f;
    float inv = 1.0f / rs;
    float u = 2.0f*(rs - RMINc)/SPANc - 1.0f;
    u = fminf(fmaxf(u, -1.0f), 1.0f);
    float rc = fminf(fmaxf(rs, RMINc), RMAXc);
    float fc = (valid && rs < RMAXc) ? 0.5f*(cosf(PI_F*(rc - RMINc)/SPANc) + 1.0f) : 0.0f;

    float T[BETAc];
    T[0] = 1.0f; T[1] = u;
#pragma unroll
    for (int k = 2; k < BETAc; k++) T[k] = 2.0f*u*T[k-1] - T[k-2];

    int tj = m >> 7;
    const float* cb = &c_sh[tj * M1c * BETAc];
    float q0 = valid ? 1.0f : 0.0f;
    float qv[4]; qv[0] = q0; qv[1] = x*inv*q0; qv[2] = y*inv*q0; qv[3] = z*inv*q0;

    float gv[M1c];
#pragma unroll
    for (int p = 0; p < M1c; p++) {
        float s = 0.0f;
#pragma unroll
        for (int k = 0; k < BETAc; k++) s += cb[p*BETAc + k] * T[k];
        gv[p] = s * fc;
    }

    int lane = m & 31;
#pragma unroll
    for (int p = 0; p < M1c; p++) {
#pragma unroll
        for (int a = 0; a < 4; a++) {
            float v = wsum(gv[p] * qv[a]);
            if (lane == 0) atomicAdd(&S_sh[p*4 + a], v);
        }
    }
    __syncthreads();

    if (m < NFEATc) {
        float s = S_sh[m] * (1.0f / Mc);
        Sn[m] = s;
        g_S[(long)bn * NFEATc + m] = s;
    }
    __syncthreads();

    float f = 0.0f;
    if (m < NFEATc) {
        int p = m >> 2, qi = m & 3;
#pragma unroll
        for (int a = 0; a < 4; a++) f += Sn[p*4 + a] * Sn[qi*4 + a];
        g_feat[(long)bn * NFEATc + m] = f;
    }
    // per-type stats (f==0 for threads >=64)
    float fs  = wsum(f);
    float f2s = wsum(f * f);
    if (lane == 0) { ps[m >> 5] = fs; ps2[m >> 5] = f2s; }
    __syncthreads();
    if (m == 0) {
        float s = 0.0f, s2 = 0.0f;
#pragma unroll
        for (int w = 0; w < 8; w++) { s += ps[w]; s2 += ps2[w]; }
        atomicAdd(&g_sum[ti],  (double)s);
        atomicAdd(&g_sumsq[ti], (double)s2);
    }
}

// ---------------- kernel 3: finalize stats -------------------------------
__global__ void stats_kernel(const int* __restrict__ tmap) {
    __shared__ int cnt[NTYPESc];
    if (threadIdx.x < NTYPESc) cnt[threadIdx.x] = 0;
    __syncthreads();
    for (int i = threadIdx.x; i < Nc; i += blockDim.x) atomicAdd(&cnt[tmap[i]], 1);
    __syncthreads();
    if (threadIdx.x == 0) {
        for (int t = 0; t < NTYPESc; t++) {
            double c   = (double)cnt[t] * Bc * NFEATc;
            double mu  = g_sum[t] / c;
            double var = (g_sumsq[t] - g_sum[t]*g_sum[t]/c) / (c - 1.0);
            g_mu[t]   = (float)mu;
            g_istd[t] = (float)(1.0 / sqrt(var));
        }
    }
}

// ---------------- kernel 4: MLP forward + backward ------------------------
#define APB 8
__global__ void mlp_kernel(const int* __restrict__ tmap,
                           const float* __restrict__ W0, const float* __restrict__ b0,
                           const float* __restrict__ W1, const float* __restrict__ b1,
                           const float* __restrict__ W2, const float* __restrict__ b2,
                           const float* __restrict__ Wout, const float* __restrict__ bout,
                           float* __restrict__ outEi, float* __restrict__ outEtot) {
    __shared__ float xs[NFEATc];
    __shared__ float h0s[Hc], h1s[Hc], vs[Hc];
    __shared__ float red[4];
    int j = threadIdx.x;

    for (int a = 0; a < APB; a++) {
        int bn = blockIdx.x * APB + a;
        int n  = bn & (Nc - 1);
        int b  = bn >> 10;
        int t  = tmap[n];
        float mu = g_mu[t], istd = g_istd[t];

        if (j < NFEATc) xs[j] = (g_feat[(long)bn*NFEATc + j] - mu) * istd;
        __syncthreads();

        const float* W0t = W0 + t*NFEATc*Hc;
        const float* W1t = W1 + t*Hc*Hc;
        const float* W2t = W2 + t*Hc*Hc;

        float z = b0[t*Hc + j];
#pragma unroll 8
        for (int p = 0; p < NFEATc; p++) z += xs[p] * W0t[p*Hc + j];
        float a0 = tanhf(z);
        h0s[j] = a0; __syncthreads();

        z = b1[t*Hc + j];
#pragma unroll 8
        for (int i = 0; i < Hc; i++) z += h0s[i] * W1t[i*Hc + j];
        float a1 = tanhf(z);
        float h1 = a1 + a0;
        h1s[j] = h1; __syncthreads();

        z = b2[t*Hc + j];
#pragma unroll 8
        for (int i = 0; i < Hc; i++) z += h1s[i] * W2t[i*Hc + j];
        float a2 = tanhf(z);
        float h2 = a2 + h1;

        float w = Wout[t*Hc + j];
        float e = wsum(h2 * w);
        if ((j & 31) == 0) red[j >> 5] = e;
        __syncthreads();
        if (j == 0) {
            float E = red[0] + red[1] + red[2] + red[3] + bout[t];
            outEi[bn] = E;
            atomicAdd(&outEtot[b], E);
        }

        // ---- backward: dE/dfeat_raw ----
        float dh2 = w;
        float v2  = dh2 * (1.0f - a2*a2);
        vs[j] = v2; __syncthreads();

        const float* W2Tt = g_W2T + t*Hc*Hc;
        float dh1 = dh2;
#pragma unroll 8
        for (int jj = 0; jj < Hc; jj++) dh1 += W2Tt[jj*Hc + j] * vs[jj];
        float v1 = dh1 * (1.0f - a1*a1);
        __syncthreads();
        vs[j] = v1; __syncthreads();

        const float* W1Tt = g_W1T + t*Hc*Hc;
        float dh0 = dh1;
#pragma unroll 8
        for (int jj = 0; jj < Hc; jj++) dh0 += W1Tt[jj*Hc + j] * vs[jj];
        float v0 = dh0 * (1.0f - a0*a0);
        __syncthreads();
        vs[j] = v0; __syncthreads();

        if (j < NFEATc) {
            const float* W0Tt = g_W0T + t*Hc*NFEATc;
            float dx = 0.0f;
#pragma unroll 8
            for (int jj = 0; jj < Hc; jj++) dx += W0Tt[jj*NFEATc + j] * vs[jj];
            g_dfeat[(long)bn*NFEATc + j] = dx * istd;
        }
        __syncthreads();
    }
}

// ---------------- kernel 5: gradient w.r.t. rvec, forces, virial ----------
__global__ void grad_kernel(const float* __restrict__ rvec,
                            const int*   __restrict__ tmap,
                            const float* __restrict__ cparam,
                            const int*   __restrict__ list_neigh,
                            float* __restrict__ Force,
                            float* __restrict__ Virial) {
    int bn = blockIdx.x;
    int n  = bn & (Nc - 1);
    int b  = bn >> 10;
    int m  = threadIdx.x;
    int ti = tmap[n];

    __shared__ float c_sh[NTYPESc*M1c*BETAc];
    __shared__ float dfs[NFEATc], Ss[NFEATc], dS_sh[NFEATc];
    __shared__ float acc[12];   // fx,fy,fz, 9 virial

    c_sh[m] = cparam[ti * (NTYPESc*M1c*BETAc) + m];
    if (m < NFEATc) {
        dfs[m] = g_dfeat[(long)bn*NFEATc + m];
        Ss[m]  = g_S[(long)bn*NFEATc + m];
    }
    if (m < 12) acc[m] = 0.0f;
    __syncthreads();

    if (m < NFEATc) {
        int r = m >> 2, a = m & 3;
        float v = 0.0f;
#pragma unroll
        for (int q = 0; q < 4; q++) v += dfs[r*4 + q] * Ss[q*4 + a];
        if (r < 4) {
#pragma unroll
            for (int p = 0; p < M1c; p++) v += dfs[p*4 + r] * Ss[p*4 + a];
        }
        dS_sh[m] = v;
    }
    __syncthreads();

    const float* rv = rvec + ((long)bn * Mc + m) * 3;
    float x = rv[0], y = rv[1], z = rv[2];
    float r = sqrtf(x*x + y*y + z*z);
    bool  valid = r > 1e-6f;
    float rs  = valid ? r : 1.0f;
    float inv = 1.0f / rs;
    float ux = x*inv, uy = y*inv, uz = z*inv;

    float u0 = 2.0f*(rs - RMINc)/SPANc - 1.0f;
    bool  uin = (u0 > -1.0f) && (u0 < 1.0f);
    float u = fminf(fmaxf(u0, -1.0f), 1.0f);
    float rc = fminf(fmaxf(rs, RMINc), RMAXc);
    float arg = PI_F*(rc - RMINc)/SPANc;
    float fc = (valid && rs < RMAXc) ? 0.5f*(cosf(arg) + 1.0f) : 0.0f;
    float dfc_dr = (valid && rs < RMAXc && rs > RMINc) ? -0.5f*PI_F/SPANc*sinf(arg) : 0.0f;
    float du_dr  = uin ? 2.0f/SPANc : 0.0f;

    float T[BETAc], D[BETAc];
    T[0] = 1.0f; T[1] = u; D[0] = 0.0f; D[1] = 1.0f;
#pragma unroll
    for (int k = 2; k < BETAc; k++) {
        T[k] = 2.0f*u*T[k-1] - T[k-2];
        D[k] = 2.0f*T[k-1] + 2.0f*u*D[k-1] - D[k-2];
    }

    int tj = m >> 7;
    const float* cb = &c_sh[tj * M1c * BETAc];
    float q0 = valid ? 1.0f : 0.0f;
    float qv[4]; qv[0] = q0; qv[1] = ux*q0; qv[2] = uy*q0; qv[3] = uz*q0;

    const float invM = 1.0f / Mc;
    float dfc = 0.0f, duP = 0.0f;
    float dux = 0.0f, duy = 0.0f, duz = 0.0f;
#pragma unroll
    for (int p = 0; p < M1c; p++) {
        float P = 0.0f, Pd = 0.0f;
#pragma unroll
        for (int k = 0; k < BETAc; k++) {
            float c = cb[p*BETAc + k];
            P  += c * T[k];
            Pd += c * D[k];
        }
        float dg = (dS_sh[p*4+0]*qv[0] + dS_sh[p*4+1]*qv[1] +
                    dS_sh[p*4+2]*qv[2] + dS_sh[p*4+3]*qv[3]) * invM;
        dfc += dg * P;
        duP += dg * Pd;
        float gp = fc * P;
        dux += dS_sh[p*4+1] * gp;
        duy += dS_sh[p*4+2] * gp;
        duz += dS_sh[p*4+3] * gp;
    }
    dux *= invM * q0; duy *= invM * q0; duz *= invM * q0;
    float du  = fc * duP;
    float drs = dfc * dfc_dr + du * du_dr;
    float dot = dux*ux + duy*uy + duz*uz;

    float fx = 0.0f, fy = 0.0f, fz = 0.0f;
    if (valid) {
        fx = drs*ux + (dux - dot*ux)*inv;
        fy = drs*uy + (duy - dot*uy)*inv;
        fz = drs*uz + (duz - dot*uz)*inv;
    }

    // neighbor scatter (per-thread atomics, addresses mostly distinct)
    int nb = list_neigh[(long)bn * Mc + m];
    if (nb > 0) {
        long fj = ((long)b * NTOT + (nb - 1)) * 3;
        atomicAdd(&Force[fj + 0], -fx);
        atomicAdd(&Force[fj + 1], -fy);
        atomicAdd(&Force[fj + 2], -fz);
    }

    // center force + virial: block reduce, then few atomics
    int lane = m & 31;
    float vals[12];
    vals[0] = fx; vals[1] = fy; vals[2] = fz;
    vals[3]  = x*fx; vals[4]  = x*fy; vals[5]  = x*fz;
    vals[6]  = y*fx; vals[7]  = y*fy; vals[8]  = y*fz;
    vals[9]  = z*fx; vals[10] = z*fy; vals[11] = z*fz;
#pragma unroll
    for (int i = 0; i < 12; i++) {
        float v = wsum(vals[i]);
        if (lane == 0) atomicAdd(&acc[i], v);
    }
    __syncthreads();
    if (m < 3)  atomicAdd(&Force[((long)b*NTOT + n)*3 + m], acc[m]);
    if (m >= 3 && m < 12) atomicAdd(&Virial[b*9 + (m - 3)], -acc[m]);
}

// ---------------- launch ---------------------------------------------------
extern "C" void kernel_launch(void* const* d_in, const int* in_sizes, int n_in,
                              void* d_out, int out_size) {
    const int*   list_neigh = (const int*)  d_in[0];
    const int*   tmap       = (const int*)  d_in[1];
    const float* rvec       = (const float*)d_in[2];
    const float* cparam     = (const float*)d_in[3];
    const float* W0         = (const float*)d_in[4];
    const float* b0         = (const float*)d_in[5];
    const float* W1         = (const float*)d_in[6];
    const float* b1         = (const float*)d_in[7];
    const float* W2         = (const float*)d_in[8];
    const float* b2         = (const float*)d_in[9];
    const float* Wout       = (const float*)d_in[10];
    const float* bout       = (const float*)d_in[11];

    float* out      = (float*)d_out;
    float* outEtot  = out + O_ETOT;
    float* outEi    = out + O_EI;
    float* outForce = out + O_FORCE;
    float* outVir   = out + O_VIR;

    zero_kernel<<<(OUT_TOTAL + 255) / 256, 256>>>(out);
    transpose_kernel<<<(NTYPESc*Hc*Hc + 255) / 256, 256>>>(W0, W1, W2);
    feat_kernel<<<Bc*Nc, 256>>>(rvec, tmap, cparam);
    stats_kernel<<<1, 256>>>(tmap);
    mlp_kernel<<<Bc*Nc / APB, Hc>>>(tmap, W0, b0, W1, b1, W2, b2, Wout, bout,
                                    outEi, outEtot);
    grad_kernel<<<Bc*Nc, 256>>>(rvec, tmap, cparam, list_neigh, outForce, outVir);
}

// round 2
// speedup vs baseline: 1.8642x; 1.8642x over previous
#include <cuda_runtime.h>
#include <math.h>

#define Bc      8
#define Nc      1024
#define NTYPESc 2
#define MNc     128
#define Mc      256          // NTYPES*MN
#define BETAc   8
#define M1c     16
#define M2c     4
#define NFEATc  64           // M1*M2
#define Hc      128
#define NGHOSTc 64
#define NTOT    (Nc + NGHOSTc)   // 1088
#define RMAXc   6.0f
#define RMINc   0.5f
#define SPANc   5.5f
#define PI_F    3.14159265358979323846f

#define O_ETOT  0
#define O_EI    (O_ETOT + Bc)                 // 8
#define O_FORCE (O_EI + Bc*Nc)                // 8200
#define O_VIR   (O_FORCE + Bc*NTOT*3)         // 34312
#define OUT_TOTAL (O_VIR + Bc*9)              // 34384

// ---------------- device scratch (no allocation allowed) ----------------
__device__ float  g_S    [Bc*Nc*NFEATc];   // S (B,N,16,4), already /M
__device__ float  g_feat [Bc*Nc*NFEATc];   // raw features
__device__ float  g_dfeat[Bc*Nc*NFEATc];   // dE/dfeat_raw (incl. 1/std)
__device__ double g_sum  [NTYPESc];
__device__ double g_sumsq[NTYPESc];
__device__ float  g_mu   [NTYPESc];
__device__ float  g_istd [NTYPESc];        // 1/std
__device__ float  g_W0T  [NTYPESc*Hc*NFEATc];  // [t][j][p]
__device__ float  g_W1T  [NTYPESc*Hc*Hc];      // [t][j][i]
__device__ float  g_W2T  [NTYPESc*Hc*Hc];

__device__ __forceinline__ float wsum(float v) {
    v += __shfl_xor_sync(0xffffffffu, v, 16);
    v += __shfl_xor_sync(0xffffffffu, v, 8);
    v += __shfl_xor_sync(0xffffffffu, v, 4);
    v += __shfl_xor_sync(0xffffffffu, v, 2);
    v += __shfl_xor_sync(0xffffffffu, v, 1);
    return v;
}

// packed butterfly step: V values -> V/2 values, component bit = lane bit OFF
template<int HALF, int OFF>
__device__ __forceinline__ void bstep(float* v, int lane) {
    bool hi = (lane & OFF) != 0;
#pragma unroll
    for (int i = 0; i < HALF; i++) {
        float send = hi ? v[i] : v[i + HALF];
        float recv = __shfl_xor_sync(0xffffffffu, send, OFF);
        v[i] = (hi ? v[i + HALF] : v[i]) + recv;
    }
}

// ---------------- kernel 0: zero outputs + accumulators -----------------
__global__ void zero_kernel(float* out) {
    int i = blockIdx.x * blockDim.x + threadIdx.x;
    if (i < OUT_TOTAL) out[i] = 0.0f;
    if (i < NTYPESc) { g_sum[i] = 0.0; g_sumsq[i] = 0.0; }
}

// ---------------- kernel 1: transpose weights ---------------------------
__global__ void transpose_kernel(const float* __restrict__ W0,
                                 const float* __restrict__ W1,
                                 const float* __restrict__ W2) {
    int i = blockIdx.x * blockDim.x + threadIdx.x;
    if (i < NTYPESc*Hc*NFEATc) {
        int t = i / (Hc*NFEATc); int r = i % (Hc*NFEATc);
        int j = r / NFEATc;      int p = r % NFEATc;
        g_W0T[i] = W0[(t*NFEATc + p)*Hc + j];
    }
    if (i < NTYPESc*Hc*Hc) {
        int t = i / (Hc*Hc); int r = i % (Hc*Hc);
        int j = r / Hc;      int k = r % Hc;
        g_W1T[i] = W1[(t*Hc + k)*Hc + j];
        g_W2T[i] = W2[(t*Hc + k)*Hc + j];
    }
}

// ---------------- kernel 2: features + per-type stats --------------------
__global__ void feat_kernel(const float* __restrict__ rvec,
                            const int*   __restrict__ tmap,
                            const float* __restrict__ cparam) {
    int bn = blockIdx.x;
    int n  = bn & (Nc - 1);
    int m  = threadIdx.x;
    int ti = tmap[n];

    __shared__ float c_sh[NTYPESc*M1c*BETAc];   // 256
    __shared__ float S_sh[NFEATc];
    __shared__ float Sn[NFEATc];
    __shared__ float ps[8], ps2[8];

    c_sh[m] = cparam[ti * (NTYPESc*M1c*BETAc) + m];
    if (m < NFEATc) S_sh[m] = 0.0f;
    __syncthreads();

    const float* rv = rvec + ((long)bn * Mc + m) * 3;
    float x = rv[0], y = rv[1], z = rv[2];
    float r = sqrtf(x*x + y*y + z*z);
    bool  valid = r > 1e-6f;
    float rs  = valid ? r : 1.0f;
    float inv = 1.0f / rs;
    float u = 2.0f*(rs - RMINc)/SPANc - 1.0f;
    u = fminf(fmaxf(u, -1.0f), 1.0f);
    float rc = fminf(fmaxf(rs, RMINc), RMAXc);
    float fc = (valid && rs < RMAXc) ? 0.5f*(cosf(PI_F*(rc - RMINc)/SPANc) + 1.0f) : 0.0f;

    float T[BETAc];
    T[0] = 1.0f; T[1] = u;
#pragma unroll
    for (int k = 2; k < BETAc; k++) T[k] = 2.0f*u*T[k-1] - T[k-2];

    int tj = m >> 7;
    const float* cb = &c_sh[tj * M1c * BETAc];
    float q0 = valid ? 1.0f : 0.0f;
    float qv[4]; qv[0] = q0; qv[1] = x*inv*q0; qv[2] = y*inv*q0; qv[3] = z*inv*q0;

    // per-thread outer products (64 components), then packed butterfly reduce
    float v[NFEATc];
#pragma unroll
    for (int p = 0; p < M1c; p++) {
        float s = 0.0f;
#pragma unroll
        for (int k = 0; k < BETAc; k++) s += cb[p*BETAc + k] * T[k];
        float gp = s * fc;
        v[p*4 + 0] = gp * qv[0];
        v[p*4 + 1] = gp * qv[1];
        v[p*4 + 2] = gp * qv[2];
        v[p*4 + 3] = gp * qv[3];
    }
    int lane = m & 31;
    bstep<32, 16>(v, lane);
    bstep<16,  8>(v, lane);
    bstep< 8,  4>(v, lane);
    bstep< 4,  2>(v, lane);
    bstep< 2,  1>(v, lane);
    // lane holds fully warp-reduced components 2*lane, 2*lane+1
    atomicAdd(&S_sh[2*lane + 0], v[0]);
    atomicAdd(&S_sh[2*lane + 1], v[1]);
    __syncthreads();

    if (m < NFEATc) {
        float s = S_sh[m] * (1.0f / Mc);
        Sn[m] = s;
        g_S[(long)bn * NFEATc + m] = s;
    }
    __syncthreads();

    float f = 0.0f;
    if (m < NFEATc) {
        int p = m >> 2, qi = m & 3;
#pragma unroll
        for (int a = 0; a < 4; a++) f += Sn[p*4 + a] * Sn[qi*4 + a];
        g_feat[(long)bn * NFEATc + m] = f;
    }
    float fs  = wsum(f);
    float f2s = wsum(f * f);
    if (lane == 0) { ps[m >> 5] = fs; ps2[m >> 5] = f2s; }
    __syncthreads();
    if (m == 0) {
        float s = 0.0f, s2 = 0.0f;
#pragma unroll
        for (int w = 0; w < 8; w++) { s += ps[w]; s2 += ps2[w]; }
        atomicAdd(&g_sum[ti],  (double)s);
        atomicAdd(&g_sumsq[ti], (double)s2);
    }
}

// ---------------- kernel 3: finalize stats -------------------------------
__global__ void stats_kernel(const int* __restrict__ tmap) {
    __shared__ int cnt[NTYPESc];
    if (threadIdx.x < NTYPESc) cnt[threadIdx.x] = 0;
    __syncthreads();
    for (int i = threadIdx.x; i < Nc; i += blockDim.x) atomicAdd(&cnt[tmap[i]], 1);
    __syncthreads();
    if (threadIdx.x == 0) {
        for (int t = 0; t < NTYPESc; t++) {
            double c   = (double)cnt[t] * Bc * NFEATc;
            double mu  = g_sum[t] / c;
            double var = (g_sumsq[t] - g_sum[t]*g_sum[t]/c) / (c - 1.0);
            g_mu[t]   = (float)mu;
            g_istd[t] = (float)(1.0 / sqrt(var));
        }
    }
}

// ---------------- kernel 4: MLP fwd+bwd, warp-per-4-atoms ----------------
__device__ __forceinline__ void fma16(float (&z)[16], float4 wv, float4 xv) {
    z[ 0] = fmaf(wv.x, xv.x, z[ 0]); z[ 1] = fmaf(wv.x, xv.y, z[ 1]);
    z[ 2] = fmaf(wv.x, xv.z, z[ 2]); z[ 3] = fmaf(wv.x, xv.w, z[ 3]);
    z[ 4] = fmaf(wv.y, xv.x, z[ 4]); z[ 5] = fmaf(wv.y, xv.y, z[ 5]);
    z[ 6] = fmaf(wv.y, xv.z, z[ 6]); z[ 7] = fmaf(wv.y, xv.w, z[ 7]);
    z[ 8] = fmaf(wv.z, xv.x, z[ 8]); z[ 9] = fmaf(wv.z, xv.y, z[ 9]);
    z[10] = fmaf(wv.z, xv.z, z[10]); z[11] = fmaf(wv.z, xv.w, z[11]);
    z[12] = fmaf(wv.w, xv.x, z[12]); z[13] = fmaf(wv.w, xv.y, z[13]);
    z[14] = fmaf(wv.w, xv.z, z[14]); z[15] = fmaf(wv.w, xv.w, z[15]);
}

#define MLP_WARPS 4
__global__ void __launch_bounds__(128) mlp_kernel(
        const int* __restrict__ tmap,
        const float* __restrict__ W0, const float* __restrict__ b0,
        const float* __restrict__ W1, const float* __restrict__ b1,
        const float* __restrict__ W2, const float* __restrict__ b2,
        const float* __restrict__ Wout, const float* __restrict__ bout,
        float* __restrict__ outEi, float* __restrict__ outEtot) {
    __shared__ float4 bufA[MLP_WARPS][Hc];
    __shared__ float4 bufB[MLP_WARPS][Hc];

    const int w   = threadIdx.x >> 5;
    const int ln  = threadIdx.x & 31;
    const int bn0 = (blockIdx.x * MLP_WARPS + w) * 4;
    const int n0  = bn0 & (Nc - 1);
    const int b   = bn0 >> 10;
    const int t   = tmap[n0];          // 4 consecutive atoms share type (sorted tmap)
    const float mu = g_mu[t], istd = g_istd[t];

    float*        Af = (float*)bufA[w];
    float*        Bf = (float*)bufB[w];
    const float4* A4 = bufA[w];
    const float4* B4 = bufB[w];

    // load normalized features, layout [p][atom]
#pragma unroll
    for (int k = 0; k < 8; k++) {
        int idx = k * 32 + ln;
        int p = idx >> 2, a = idx & 3;
        Af[idx] = (g_feat[(size_t)(bn0 + a) * NFEATc + p] - mu) * istd;
    }
    __syncwarp();

    const float4* W0f  = (const float4*)(W0    + (size_t)t * NFEATc * Hc);
    const float4* W1f  = (const float4*)(W1    + (size_t)t * Hc * Hc);
    const float4* W2f  = (const float4*)(W2    + (size_t)t * Hc * Hc);
    const float4* W1Tf = (const float4*)(g_W1T + (size_t)t * Hc * Hc);
    const float4* W2Tf = (const float4*)(g_W2T + (size_t)t * Hc * Hc);
    const float2* W0T2 = (const float2*)(g_W0T + (size_t)t * Hc * NFEATc);

    float acc[16], a0r[16], a1r[16], a2r[16];

    // ---- layer 0: 64 -> 128 ----
    {
        float4 bb = ((const float4*)(b0 + t * Hc))[ln];
#pragma unroll
        for (int a = 0; a < 4; a++) {
            acc[0+a] = bb.x; acc[4+a] = bb.y; acc[8+a] = bb.z; acc[12+a] = bb.w;
        }
    }
#pragma unroll 8
    for (int p = 0; p < NFEATc; p++) fma16(acc, W0f[p*32 + ln], A4[p]);
#pragma unroll
    for (int i = 0; i < 16; i++) a0r[i] = tanhf(acc[i]);
#pragma unroll
    for (int c = 0; c < 4; c++)
        bufB[w][4*ln + c] = make_float4(a0r[c*4+0], a0r[c*4+1], a0r[c*4+2], a0r[c*4+3]);
    __syncwarp();

    // ---- layer 1 ----
    {
        float4 bb = ((const float4*)(b1 + t * Hc))[ln];
#pragma unroll
        for (int a = 0; a < 4; a++) {
            acc[0+a] = bb.x; acc[4+a] = bb.y; acc[8+a] = bb.z; acc[12+a] = bb.w;
        }
    }
#pragma unroll 8
    for (int p = 0; p < Hc; p++) fma16(acc, W1f[p*32 + ln], B4[p]);
    float h1r[16];
#pragma unroll
    for (int i = 0; i < 16; i++) { a1r[i] = tanhf(acc[i]); h1r[i] = a1r[i] + a0r[i]; }
#pragma unroll
    for (int c = 0; c < 4; c++)
        bufA[w][4*ln + c] = make_float4(h1r[c*4+0], h1r[c*4+1], h1r[c*4+2], h1r[c*4+3]);
    __syncwarp();

    // ---- layer 2 ----
    {
        float4 bb = ((const float4*)(b2 + t * Hc))[ln];
#pragma unroll
        for (int a = 0; a < 4; a++) {
            acc[0+a] = bb.x; acc[4+a] = bb.y; acc[8+a] = bb.z; acc[12+a] = bb.w;
        }
    }
#pragma unroll 8
    for (int p = 0; p < Hc; p++) fma16(acc, W2f[p*32 + ln], A4[p]);
#pragma unroll
    for (int i = 0; i < 16; i++) a2r[i] = tanhf(acc[i]);

    // ---- energy ----
    float4 wo = ((const float4*)(Wout + t * Hc))[ln];
    float e0, e1, e2, e3;
    {
        float h2[16];
#pragma unroll
        for (int i = 0; i < 16; i++) h2[i] = a2r[i] + h1r[i];
        e0 = wo.x*h2[0] + wo.y*h2[4] + wo.z*h2[ 8] + wo.w*h2[12];
        e1 = wo.x*h2[1] + wo.y*h2[5] + wo.z*h2[ 9] + wo.w*h2[13];
        e2 = wo.x*h2[2] + wo.y*h2[6] + wo.z*h2[10] + wo.w*h2[14];
        e3 = wo.x*h2[3] + wo.y*h2[7] + wo.z*h2[11] + wo.w*h2[15];
    }
    e0 = wsum(e0); e1 = wsum(e1); e2 = wsum(e2); e3 = wsum(e3);
    float bo = bout[t];
    if (ln < 4) {
        float myE = (ln == 0) ? e0 : (ln == 1) ? e1 : (ln == 2) ? e2 : e3;
        outEi[bn0 + ln] = myE + bo;
    }
    if (ln == 0) atomicAdd(&outEtot[b], e0 + e1 + e2 + e3 + 4.0f * bo);

    // ---- backward ----
    // v2 = wo(c) * (1 - a2^2) -> B
#pragma unroll
    for (int c = 0; c < 4; c++) {
        float wc = (c == 0) ? wo.x : (c == 1) ? wo.y : (c == 2) ? wo.z : wo.w;
        bufB[w][4*ln + c] = make_float4(wc * (1.0f - a2r[c*4+0]*a2r[c*4+0]),
                                        wc * (1.0f - a2r[c*4+1]*a2r[c*4+1]),
                                        wc * (1.0f - a2r[c*4+2]*a2r[c*4+2]),
                                        wc * (1.0f - a2r[c*4+3]*a2r[c*4+3]));
    }
    __syncwarp();

    float dh[16];  // dE/dh1 (then reused as dE/dh0)
#pragma unroll
    for (int c = 0; c < 4; c++) {
        float wc = (c == 0) ? wo.x : (c == 1) ? wo.y : (c == 2) ? wo.z : wo.w;
        dh[c*4+0] = wc; dh[c*4+1] = wc; dh[c*4+2] = wc; dh[c*4+3] = wc;
    }
#pragma unroll 8
    for (int j = 0; j < Hc; j++) fma16(dh, W2Tf[j*32 + ln], B4[j]);

    // v1 = dh1 * (1 - a1^2) -> A
#pragma unroll
    for (int c = 0; c < 4; c++)
        bufA[w][4*ln + c] = make_float4(dh[c*4+0] * (1.0f - a1r[c*4+0]*a1r[c*4+0]),
                                        dh[c*4+1] * (1.0f - a1r[c*4+1]*a1r[c*4+1]),
                                        dh[c*4+2] * (1.0f - a1r[c*4+2]*a1r[c*4+2]),
                                        dh[c*4+3] * (1.0f - a1r[c*4+3]*a1r[c*4+3]));
    __syncwarp();

#pragma unroll 8
    for (int j = 0; j < Hc; j++) fma16(dh, W1Tf[j*32 + ln], A4[j]);

    // v0 = dh0 * (1 - a0^2) -> B
#pragma unroll
    for (int c = 0; c < 4; c++)
        bufB[w][4*ln + c] = make_float4(dh[c*4+0] * (1.0f - a0r[c*4+0]*a0r[c*4+0]),
                                        dh[c*4+1] * (1.0f - a0r[c*4+1]*a0r[c*4+1]),
                                        dh[c*4+2] * (1.0f - a0r[c*4+2]*a0r[c*4+2]),
                                        dh[c*4+3] * (1.0f - a0r[c*4+3]*a0r[c*4+3]));
    __syncwarp();

    // dx_p = sum_j W0T[j][p] * v0[j], thread owns p = 2ln, 2ln+1
    float dx0[4] = {0,0,0,0}, dx1[4] = {0,0,0,0};
#pragma unroll 8
    for (int j = 0; j < Hc; j++) {
        float2 w2 = W0T2[j*32 + ln];
        float4 vv = B4[j];
        dx0[0] = fmaf(w2.x, vv.x, dx0[0]); dx0[1] = fmaf(w2.x, vv.y, dx0[1]);
        dx0[2] = fmaf(w2.x, vv.z, dx0[2]); dx0[3] = fmaf(w2.x, vv.w, dx0[3]);
        dx1[0] = fmaf(w2.y, vv.x, dx1[0]); dx1[1] = fmaf(w2.y, vv.y, dx1[1]);
        dx1[2] = fmaf(w2.y, vv.z, dx1[2]); dx1[3] = fmaf(w2.y, vv.w, dx1[3]);
    }
#pragma unroll
    for (int a = 0; a < 4; a++) {
        ((float2*)g_dfeat)[(size_t)(bn0 + a) * (NFEATc/2) + ln] =
            make_float2(dx0[a] * istd, dx1[a] * istd);
    }
}

// ---------------- kernel 5: gradient w.r.t. rvec, forces, virial ----------
__global__ void grad_kernel(const float* __restrict__ rvec,
                            const int*   __restrict__ tmap,
                            const float* __restrict__ cparam,
                            const int*   __restrict__ list_neigh,
                            float* __restrict__ Force,
                            float* __restrict__ Virial) {
    int bn = blockIdx.x;
    int n  = bn & (Nc - 1);
    int b  = bn >> 10;
    int m  = threadIdx.x;
    int ti = tmap[n];

    __shared__ float c_sh[NTYPESc*M1c*BETAc];
    __shared__ float dfs[NFEATc], Ss[NFEATc], dS_sh[NFEATc];
    __shared__ float acc[12];

    c_sh[m] = cparam[ti * (NTYPESc*M1c*BETAc) + m];
    if (m < NFEATc) {
        dfs[m] = g_dfeat[(long)bn*NFEATc + m];
        Ss[m]  = g_S[(long)bn*NFEATc + m];
    }
    if (m < 12) acc[m] = 0.0f;
    __syncthreads();

    if (m < NFEATc) {
        int r = m >> 2, a = m & 3;
        float v = 0.0f;
#pragma unroll
        for (int q = 0; q < 4; q++) v += dfs[r*4 + q] * Ss[q*4 + a];
        if (r < 4) {
#pragma unroll
            for (int p = 0; p < M1c; p++) v += dfs[p*4 + r] * Ss[p*4 + a];
        }
        dS_sh[m] = v;
    }
    __syncthreads();

    const float* rv = rvec + ((long)bn * Mc + m) * 3;
    float x = rv[0], y = rv[1], z = rv[2];
    float r = sqrtf(x*x + y*y + z*z);
    bool  valid = r > 1e-6f;
    float rs  = valid ? r : 1.0f;
    float inv = 1.0f / rs;
    float ux = x*inv, uy = y*inv, uz = z*inv;

    float u0 = 2.0f*(rs - RMINc)/SPANc - 1.0f;
    bool  uin = (u0 > -1.0f) && (u0 < 1.0f);
    float u = fminf(fmaxf(u0, -1.0f), 1.0f);
    float rc = fminf(fmaxf(rs, RMINc), RMAXc);
    float arg = PI_F*(rc - RMINc)/SPANc;
    float fc = (valid && rs < RMAXc) ? 0.5f*(cosf(arg) + 1.0f) : 0.0f;
    float dfc_dr = (valid && rs < RMAXc && rs > RMINc) ? -0.5f*PI_F/SPANc*sinf(arg) : 0.0f;
    float du_dr  = uin ? 2.0f/SPANc : 0.0f;

    float T[BETAc], D[BETAc];
    T[0] = 1.0f; T[1] = u; D[0] = 0.0f; D[1] = 1.0f;
#pragma unroll
    for (int k = 2; k < BETAc; k++) {
        T[k] = 2.0f*u*T[k-1] - T[k-2];
        D[k] = 2.0f*T[k-1] + 2.0f*u*D[k-1] - D[k-2];
    }

    int tj = m >> 7;
    const float* cb = &c_sh[tj * M1c * BETAc];
    float q0 = valid ? 1.0f : 0.0f;
    float qv[4]; qv[0] = q0; qv[1] = ux*q0; qv[2] = uy*q0; qv[3] = uz*q0;

    const float invM = 1.0f / Mc;
    float dfc = 0.0f, duP = 0.0f;
    float dux = 0.0f, duy = 0.0f, duz = 0.0f;
#pragma unroll
    for (int p = 0; p < M1c; p++) {
        float P = 0.0f, Pd = 0.0f;
#pragma unroll
        for (int k = 0; k < BETAc; k++) {
            float c = cb[p*BETAc + k];
            P  += c * T[k];
            Pd += c * D[k];
        }
        float dg = (dS_sh[p*4+0]*qv[0] + dS_sh[p*4+1]*qv[1] +
                    dS_sh[p*4+2]*qv[2] + dS_sh[p*4+3]*qv[3]) * invM;
        dfc += dg * P;
        duP += dg * Pd;
        float gp = fc * P;
        dux += dS_sh[p*4+1] * gp;
        duy += dS_sh[p*4+2] * gp;
        duz += dS_sh[p*4+3] * gp;
    }
    dux *= invM * q0; duy *= invM * q0; duz *= invM * q0;
    float du  = fc * duP;
    float drs = dfc * dfc_dr + du * du_dr;
    float dot = dux*ux + duy*uy + duz*uz;

    float fx = 0.0f, fy = 0.0f, fz = 0.0f;
    if (valid) {
        fx = drs*ux + (dux - dot*ux)*inv;
        fy = drs*uy + (duy - dot*uy)*inv;
        fz = drs*uz + (duz - dot*uz)*inv;
    }

    int nb = list_neigh[(long)bn * Mc + m];
    if (nb > 0) {
        long fj = ((long)b * NTOT + (nb - 1)) * 3;
        atomicAdd(&Force[fj + 0], -fx);
        atomicAdd(&Force[fj + 1], -fy);
        atomicAdd(&Force[fj + 2], -fz);
    }

    int lane = m & 31;
    float vals[12];
    vals[0] = fx; vals[1] = fy; vals[2] = fz;
    vals[3]  = x*fx; vals[4]  = x*fy; vals[5]  = x*fz;
    vals[6]  = y*fx; vals[7]  = y*fy; vals[8]  = y*fz;
    vals[9]  = z*fx; vals[10] = z*fy; vals[11] = z*fz;
#pragma unroll
    for (int i = 0; i < 12; i++) {
        float v = wsum(vals[i]);
        if (lane == 0) atomicAdd(&acc[i], v);
    }
    __syncthreads();
    if (m < 3)  atomicAdd(&Force[((long)b*NTOT + n)*3 + m], acc[m]);
    if (m >= 3 && m < 12) atomicAdd(&Virial[b*9 + (m - 3)], -acc[m]);
}

// ---------------- launch ---------------------------------------------------
extern "C" void kernel_launch(void* const* d_in, const int* in_sizes, int n_in,
                              void* d_out, int out_size) {
    const int*   list_neigh = (const int*)  d_in[0];
    const int*   tmap       = (const int*)  d_in[1];
    const float* rvec       = (const float*)d_in[2];
    const float* cparam     = (const float*)d_in[3];
    const float* W0         = (const float*)d_in[4];
    const float* b0         = (const float*)d_in[5];
    const float* W1         = (const float*)d_in[6];
    const float* b1         = (const float*)d_in[7];
    const float* W2         = (const float*)d_in[8];
    const float* b2         = (const float*)d_in[9];
    const float* Wout       = (const float*)d_in[10];
    const float* bout       = (const float*)d_in[11];

    float* out      = (float*)d_out;
    float* outEtot  = out + O_ETOT;
    float* outEi    = out + O_EI;
    float* outForce = out + O_FORCE;
    float* outVir   = out + O_VIR;

    zero_kernel<<<(OUT_TOTAL + 255) / 256, 256>>>(out);
    transpose_kernel<<<(NTYPESc*Hc*Hc + 255) / 256, 256>>>(W0, W1, W2);
    feat_kernel<<<Bc*Nc, 256>>>(rvec, tmap, cparam);
    stats_kernel<<<1, 256>>>(tmap);
    mlp_kernel<<<Bc*Nc / (MLP_WARPS*4), 128>>>(tmap, W0, b0, W1, b1, W2, b2,
                                               Wout, bout, outEi, outEtot);
    grad_kernel<<<Bc*Nc, 256>>>(rvec, tmap, cparam, list_neigh, outForce, outVir);
}